// round 9
// baseline (speedup 1.0000x reference)
#include <cuda_runtime.h>
#include <cuda_fp16.h>
#include <cstdint>

#define BSZ  512
#define SRCN 36
#define HD   1024
#define MD   4096
#define NTOK (BSZ*SRCN)       // 18432
#define ALPHA_F 8.0f
#define INV_ALPHA_F 0.125f
#define GAMMA_F 0.98f

// ---------------- scratch (device globals: allocation-guard safe) ----------
__device__ float g_ru_sum;
__device__ __align__(16) float  g_mm [(size_t)NTOK * HD];
__device__ __align__(16) __half g_mmh[(size_t)NTOK * HD];
__device__ __align__(16) __half g_h  [(size_t)NTOK * MD];
__device__ __align__(16) float  g_fc [(size_t)NTOK * HD];
__device__ __align__(16) __half g_W1h[(size_t)HD * MD];
__device__ __align__(16) __half g_W2h[(size_t)MD * HD];

// ---------------- PTX helpers ------------------------------------------------
__device__ __forceinline__ uint32_t smem_u32(const void* p) {
    uint32_t a;
    asm("{ .reg .u64 t; cvta.to.shared.u64 t, %1; cvt.u32.u64 %0, t; }" : "=r"(a) : "l"(p));
    return a;
}
__device__ __forceinline__ void cp16(uint32_t dst, const void* src) {
    asm volatile("cp.async.cg.shared.global [%0], [%1], 16;" :: "r"(dst), "l"(src));
}
__device__ __forceinline__ void cp_commit() {
    asm volatile("cp.async.commit_group;" ::: "memory");
}
template <int N>
__device__ __forceinline__ void cp_wait() {
    asm volatile("cp.async.wait_group %0;" :: "n"(N) : "memory");
}
__device__ __forceinline__ void ldsm_x4(uint32_t* r, uint32_t addr) {
    asm volatile("ldmatrix.sync.aligned.m8n8.x4.shared.b16 {%0,%1,%2,%3}, [%4];"
                 : "=r"(r[0]), "=r"(r[1]), "=r"(r[2]), "=r"(r[3]) : "r"(addr));
}
__device__ __forceinline__ void ldsm_x4_t(uint32_t* r, uint32_t addr) {
    asm volatile("ldmatrix.sync.aligned.m8n8.x4.trans.shared.b16 {%0,%1,%2,%3}, [%4];"
                 : "=r"(r[0]), "=r"(r[1]), "=r"(r[2]), "=r"(r[3]) : "r"(addr));
}
__device__ __forceinline__ void mma_f16(float* c, const uint32_t* a, const uint32_t* b) {
    asm volatile(
        "mma.sync.aligned.m16n8k16.row.col.f32.f16.f16.f32 "
        "{%0,%1,%2,%3},{%4,%5,%6,%7},{%8,%9},{%0,%1,%2,%3};"
        : "+f"(c[0]), "+f"(c[1]), "+f"(c[2]), "+f"(c[3])
        : "r"(a[0]), "r"(a[1]), "r"(a[2]), "r"(a[3]), "r"(b[0]), "r"(b[1]));
}

// ============================ fp16 HMMA GEMM =================================
// C[M,N] = A[M,K] * B[K,N]; A half [M][K] row-major, B half [K][N] row-major.
// Block 128x128, warp tile 64x32 (2x4 warps), k-chunk 32 halves, 7 stages,
// 3 k-tiles per barrier. Per group (kt..kt+2): prefetch kt+4..kt+6, writing
// buffers (kt+4..6)%7 — distinct (mod 7) from the group's read buffers, and
// their prior contents (tiles kt-3..kt-1) were consumed before this barrier.
#define TM 128
#define TN 128
#define TKH 32
#define NSTAGE 7
#define A_STG 8192            // 64 superrows * 128B (2 rows packed per 128B)
#define B_STG 8192            // 32 rows * 256B
#define STG (A_STG + B_STG)   // 16384
#define SMEM_DYN (NSTAGE * STG)   // 114688

// A smem offset for (row, 16B-chunk c16 in 0..3)
__device__ __forceinline__ uint32_t a_off(int row, int c16) {
    const int sr = row >> 1;
    const int ch = (row & 1) * 4 + c16;
    return (uint32_t)(sr * 128 + ((ch ^ (sr & 7)) << 4));
}
// B smem offset for (k row, 16B-chunk c16 in 0..15)
__device__ __forceinline__ uint32_t b_off(int k, int c16) {
    return (uint32_t)(A_STG + k * 256 + (((c16 & 8) | ((c16 ^ k) & 7)) << 4));
}

template <int OUT_HALF, int RELU>
__global__ __launch_bounds__(256, 2) void hgemm(
    const __half* __restrict__ A, const __half* __restrict__ B,
    const float* __restrict__ bias, void* __restrict__ Cout,
    int M, int N, int K) {

    extern __shared__ char sm[];
    const uint32_t base = smem_u32(sm);
    const int tid  = threadIdx.x;
    const int lane = tid & 31;
    const int warp = tid >> 5;
    const int wm = warp >> 2, wn = warp & 3;       // 2 x 4 warps, warp tile 64x32
    const int bm0 = blockIdx.y * TM;
    const int bn0 = blockIdx.x * TN;

    // cp.async slots: 2 A chunks + 2 B chunks per thread per ktile
    uint32_t a_rel[2]; const __half* a_src[2];
    #pragma unroll
    for (int i = 0; i < 2; i++) {
        const int id = tid * 2 + i;
        const int r = id >> 2, c = id & 3;
        a_rel[i] = a_off(r, c);
        a_src[i] = A + (size_t)(bm0 + r) * K + c * 8;
    }
    uint32_t b_rel[2]; const __half* b_src[2];
    #pragma unroll
    for (int i = 0; i < 2; i++) {
        const int id = tid * 2 + i;
        const int k = id >> 4, c = id & 15;
        b_rel[i] = b_off(k, c);
        b_src[i] = B + (size_t)k * N + bn0 + c * 8;
    }

    float acc[4][4][4];
    #pragma unroll
    for (int mi = 0; mi < 4; mi++)
        #pragma unroll
        for (int ni = 0; ni < 4; ni++)
            #pragma unroll
            for (int j = 0; j < 4; j++) acc[mi][ni][j] = 0.f;

    const int T = K / TKH;

    auto stage = [&](int s, int kt) {
        const int k0 = kt * TKH;
        const uint32_t sb = base + s * STG;
        #pragma unroll
        for (int i = 0; i < 2; i++) cp16(sb + a_rel[i], a_src[i] + k0);
        #pragma unroll
        for (int i = 0; i < 2; i++) cp16(sb + b_rel[i], b_src[i] + (size_t)k0 * N);
        cp_commit();
    };

    const int l_lo = lane & 15;
    const int l_hi = lane >> 4;

    auto compute = [&](int kt) {
        const uint32_t buf = base + (kt % NSTAGE) * STG;
        #pragma unroll
        for (int ks = 0; ks < 2; ks++) {
            uint32_t af[4][4];
            #pragma unroll
            for (int mi = 0; mi < 4; mi++) {
                const int row = wm * 64 + mi * 16 + l_lo;
                ldsm_x4(af[mi], buf + a_off(row, ks * 2 + l_hi));
            }
            uint32_t bf[4][2];
            #pragma unroll
            for (int p = 0; p < 2; p++) {
                const int kl = ks * 16 + l_lo;
                const int nc = wn * 4 + p * 2 + l_hi;
                uint32_t r[4];
                ldsm_x4_t(r, buf + b_off(kl, nc));
                bf[p * 2][0]     = r[0]; bf[p * 2][1]     = r[1];
                bf[p * 2 + 1][0] = r[2]; bf[p * 2 + 1][1] = r[3];
            }
            #pragma unroll
            for (int mi = 0; mi < 4; mi++)
                #pragma unroll
                for (int ni = 0; ni < 4; ni++)
                    mma_f16(acc[mi][ni], af[mi], bf[ni]);
        }
    };

    // prologue: 4 stages in flight (tiles 0..3)
    #pragma unroll
    for (int s = 0; s < 4; s++) stage(s, s);

    // main loop: one barrier per 3 k-tiles
    int kt = 0;
    for (; kt + 3 <= T; kt += 3) {
        cp_wait<1>();          // groups for tiles kt..kt+2 complete
        __syncthreads();       // publish; orders prev-group computes
        const int n1 = kt + 4;
        if (n1 < T) stage(n1 % NSTAGE, n1);
        compute(kt);
        const int n2 = kt + 5;
        if (n2 < T) stage(n2 % NSTAGE, n2);
        compute(kt + 1);
        const int n3 = kt + 6;
        if (n3 < T) stage(n3 % NSTAGE, n3);
        compute(kt + 2);
    }
    // tail (T % 3 tiles)
    if (kt < T) {
        cp_wait<0>();
        __syncthreads();
        for (; kt < T; kt++) compute(kt);
    }

    // ---- epilogue ----
    #pragma unroll
    for (int mi = 0; mi < 4; mi++) {
        const int r0 = bm0 + wm * 64 + mi * 16 + (lane >> 2);
        #pragma unroll
        for (int ni = 0; ni < 4; ni++) {
            const int cb = bn0 + wn * 32 + ni * 8 + (lane & 3) * 2;
            const float bb0 = bias[cb], bb1 = bias[cb + 1];
            float v0 = acc[mi][ni][0] + bb0;
            float v1 = acc[mi][ni][1] + bb1;
            float v2 = acc[mi][ni][2] + bb0;
            float v3 = acc[mi][ni][3] + bb1;
            if (RELU) {
                v0 = fmaxf(v0, 0.f); v1 = fmaxf(v1, 0.f);
                v2 = fmaxf(v2, 0.f); v3 = fmaxf(v3, 0.f);
            }
            if (OUT_HALF) {
                __half* Ch = (__half*)Cout;
                *(__half2*)&Ch[(size_t)r0 * N + cb]       = __floats2half2_rn(v0, v1);
                *(__half2*)&Ch[(size_t)(r0 + 8) * N + cb] = __floats2half2_rn(v2, v3);
            } else {
                float* Cf = (float*)Cout;
                *(float2*)&Cf[(size_t)r0 * N + cb]       = make_float2(v0, v1);
                *(float2*)&Cf[(size_t)(r0 + 8) * N + cb] = make_float2(v2, v3);
            }
        }
    }
}

// ---------------- convert both W1 and W2 to half (one launch) ----------------
__global__ void k_tohalf2(const float* __restrict__ W1, const float* __restrict__ W2,
                          __half* __restrict__ W1h, __half* __restrict__ W2h) {
    const int n4 = HD * MD / 4;   // per matrix
    const int i = blockIdx.x * blockDim.x + threadIdx.x;
    const float* in; __half* out; int j;
    if (i < n4)      { in = W1; out = W1h; j = i; }
    else if (i < 2 * n4) { in = W2; out = W2h; j = i - n4; }
    else return;
    float4 f = ((const float4*)in)[j];
    ((__half2*)out)[j * 2]     = __floats2half2_rn(f.x, f.y);
    ((__half2*)out)[j * 2 + 1] = __floats2half2_rn(f.z, f.w);
}

// ---------------- K: sum(ru) ---------------------------------------------------
__global__ void k_ru_sum(const float* __restrict__ ru) {
    __shared__ float sh[256];
    float s = 0.f;
    for (int i = threadIdx.x; i < NTOK; i += 256) s += ru[i];
    sh[threadIdx.x] = s;
    __syncthreads();
    for (int o = 128; o > 0; o >>= 1) {
        if (threadIdx.x < o) sh[threadIdx.x] += sh[threadIdx.x + o];
        __syncthreads();
    }
    if (threadIdx.x == 0) g_ru_sum = sh[0];
}

// ------- K: fused gate + mm = w * LN(v+q) (writes mm fp32 + fp16, ru_out) -----
__global__ void k_ln1g(const float* __restrict__ v, const float* __restrict__ q,
                       const float* __restrict__ g1, const float* __restrict__ b1,
                       const float* __restrict__ att, const float* __restrict__ ru,
                       float* __restrict__ mm, __half* __restrict__ mmh,
                       float* __restrict__ ru_out) {
    const int t = blockIdx.x;
    const int b = t / SRCN;
    const int s = t - b * SRCN;

    __shared__ float rg_s[SRCN], rn_s[SRCN];
    __shared__ float wv_sh;

    if (threadIdx.x < SRCN) {
        const int j = threadIdx.x;
        const float* arow = att + ((size_t)b * SRCN + j) * SRCN;
        float rg = 0.f;
        #pragma unroll
        for (int k = 0; k < SRCN; k++) rg += arow[k];
        const float base = ru[b * SRCN + j] * GAMMA_F + rg;
        rg_s[j] = rg;
        rn_s[j] = (g_ru_sum == 0.0f) ? base : base / (1.0f + GAMMA_F);
    }
    __syncthreads();
    if (threadIdx.x == 0) {
        float S = 0.f, T = 0.f;
        #pragma unroll
        for (int j = 0; j < SRCN; j++) {
            const float sa = sqrtf(rn_s[j]);
            S += sa;
            T += rn_s[j] * sa;
        }
        const float rn = rn_s[s], rg = rg_s[s];
        const float rm = (rn * S - T > 0.0f) ? 1.0f : 0.0f;
        ru_out[t] = ALPHA_F * rn * rm + INV_ALPHA_F * rn * (1.0f - rm);
        wv_sh     = ALPHA_F * rg * rm + INV_ALPHA_F * rg * (1.0f - rm);
    }

    const float* vp = v + (size_t)t * HD;
    const float* qp = q + (size_t)t * HD;
    float x[4];
    float sm1 = 0.f, sm2 = 0.f;
    #pragma unroll
    for (int i = 0; i < 4; i++) {
        const int c = i * 256 + threadIdx.x;
        x[i] = vp[c] + qp[c];
        sm1 += x[i];
        sm2 += x[i] * x[i];
    }
    __shared__ float sh1[8], sh2[8];
    const int lane = threadIdx.x & 31, wid = threadIdx.x >> 5;
    #pragma unroll
    for (int o = 16; o > 0; o >>= 1) {
        sm1 += __shfl_xor_sync(0xffffffffu, sm1, o);
        sm2 += __shfl_xor_sync(0xffffffffu, sm2, o);
    }
    if (lane == 0) { sh1[wid] = sm1; sh2[wid] = sm2; }
    __syncthreads();
    if (threadIdx.x == 0) {
        float a = 0.f, c = 0.f;
        #pragma unroll
        for (int i = 0; i < 8; i++) { a += sh1[i]; c += sh2[i]; }
        sh1[0] = a; sh2[0] = c;
    }
    __syncthreads();
    sm1 = sh1[0]; sm2 = sh2[0];
    const float mu   = sm1 * (1.0f / HD);
    const float var  = sm2 * (1.0f / HD) - mu * mu;
    const float rstd = rsqrtf(var + 1e-6f);
    const float ww   = wv_sh;
    #pragma unroll
    for (int i = 0; i < 4; i++) {
        const int c = i * 256 + threadIdx.x;
        const float y = ww * (g1[c] * (x[i] - mu) * rstd + b1[c]);
        mm [(size_t)t * HD + c] = y;
        mmh[(size_t)t * HD + c] = __float2half_rn(y);
    }
}

// ---------------- K: out = LN(mm + fc) -----------------------------------------
__global__ void k_ln2(const float* __restrict__ mm, const float* __restrict__ fc,
                      const float* __restrict__ g2, const float* __restrict__ b2,
                      float* __restrict__ out) {
    const int t = blockIdx.x;
    const float* mp = mm + (size_t)t * HD;
    const float* fp = fc + (size_t)t * HD;
    float x[4];
    float s = 0.f, s2 = 0.f;
    #pragma unroll
    for (int i = 0; i < 4; i++) {
        const int c = i * 256 + threadIdx.x;
        x[i] = mp[c] + fp[c];
        s += x[i];
        s2 += x[i] * x[i];
    }
    __shared__ float sh1[8], sh2[8];
    const int lane = threadIdx.x & 31, wid = threadIdx.x >> 5;
    #pragma unroll
    for (int o = 16; o > 0; o >>= 1) {
        s  += __shfl_xor_sync(0xffffffffu, s,  o);
        s2 += __shfl_xor_sync(0xffffffffu, s2, o);
    }
    if (lane == 0) { sh1[wid] = s; sh2[wid] = s2; }
    __syncthreads();
    if (threadIdx.x == 0) {
        float a = 0.f, b = 0.f;
        #pragma unroll
        for (int i = 0; i < 8; i++) { a += sh1[i]; b += sh2[i]; }
        sh1[0] = a; sh2[0] = b;
    }
    __syncthreads();
    s = sh1[0]; s2 = sh2[0];
    const float mu   = s * (1.0f / HD);
    const float var  = s2 * (1.0f / HD) - mu * mu;
    const float rstd = rsqrtf(var + 1e-6f);
    #pragma unroll
    for (int i = 0; i < 4; i++) {
        const int c = i * 256 + threadIdx.x;
        out[(size_t)t * HD + c] = g2[c] * (x[i] - mu) * rstd + b2[c];
    }
}

// ---------------- launch --------------------------------------------------------
extern "C" void kernel_launch(void* const* d_in, const int* in_sizes, int n_in,
                              void* d_out, int out_size) {
    const float* v   = (const float*)d_in[0];
    const float* q   = (const float*)d_in[1];
    const float* att = (const float*)d_in[2];
    const float* ru  = (const float*)d_in[3];
    const float* g1  = (const float*)d_in[4];
    const float* b1  = (const float*)d_in[5];
    const float* g2  = (const float*)d_in[6];
    const float* b2  = (const float*)d_in[7];
    const float* W1  = (const float*)d_in[8];
    const float* c1  = (const float*)d_in[9];
    const float* W2  = (const float*)d_in[10];
    const float* c2  = (const float*)d_in[11];

    float* out    = (float*)d_out;
    float* ru_out = out + (size_t)NTOK * HD;

    void *pmm, *pmmh, *ph, *pfc, *pw1h, *pw2h;
    cudaGetSymbolAddress(&pmm,  g_mm);
    cudaGetSymbolAddress(&pmmh, g_mmh);
    cudaGetSymbolAddress(&ph,   g_h);
    cudaGetSymbolAddress(&pfc,  g_fc);
    cudaGetSymbolAddress(&pw1h, g_W1h);
    cudaGetSymbolAddress(&pw2h, g_W2h);

    cudaFuncSetAttribute(hgemm<1, 1>, cudaFuncAttributeMaxDynamicSharedMemorySize, SMEM_DYN);
    cudaFuncSetAttribute(hgemm<0, 0>, cudaFuncAttributeMaxDynamicSharedMemorySize, SMEM_DYN);

    // launch #1: weight converts (both)
    const int nconv = 2 * (HD * MD / 4);
    k_tohalf2<<<(nconv + 255) / 256, 256>>>(W1, W2, (__half*)pw1h, (__half*)pw2h);
    // launch #2: ru sum
    k_ru_sum<<<1, 256>>>(ru);
    // launch #3: fused gate + LN1
    k_ln1g<<<NTOK, 256>>>(v, q, g1, b1, att, ru,
                          (float*)pmm, (__half*)pmmh, ru_out);
    // launch #4: GEMM1 (profiled)
    hgemm<1, 1><<<dim3(MD / TN, NTOK / TM), 256, SMEM_DYN>>>(
        (const __half*)pmmh, (const __half*)pw1h, c1, ph, NTOK, MD, HD);
    // launch #5: GEMM2
    hgemm<0, 0><<<dim3(HD / TN, NTOK / TM), 256, SMEM_DYN>>>(
        (const __half*)ph, (const __half*)pw2h, c2, pfc, NTOK, HD, MD);
    // launch #6: LN2
    k_ln2<<<NTOK, 256>>>((const float*)pmm, (const float*)pfc, g2, b2, out);
}

// round 10
// speedup vs baseline: 1.0728x; 1.0728x over previous
#include <cuda_runtime.h>
#include <cuda_fp16.h>
#include <cstdint>

#define BSZ  512
#define SRCN 36
#define HD   1024
#define MD   4096
#define NTOK (BSZ*SRCN)       // 18432
#define ALPHA_F 8.0f
#define INV_ALPHA_F 0.125f
#define GAMMA_F 0.98f

// ---------------- scratch (device globals: allocation-guard safe) ----------
__device__ float g_ru_sum;
__device__ __align__(16) __half g_mmh[(size_t)NTOK * HD];
__device__ __align__(16) __half g_h  [(size_t)NTOK * MD];
__device__ __align__(16) float  g_fc [(size_t)NTOK * HD];
__device__ __align__(16) __half g_W1h[(size_t)HD * MD];
__device__ __align__(16) __half g_W2h[(size_t)MD * HD];

// ---------------- PTX helpers ------------------------------------------------
__device__ __forceinline__ uint32_t smem_u32(const void* p) {
    uint32_t a;
    asm("{ .reg .u64 t; cvta.to.shared.u64 t, %1; cvt.u32.u64 %0, t; }" : "=r"(a) : "l"(p));
    return a;
}
__device__ __forceinline__ void cp16(uint32_t dst, const void* src) {
    asm volatile("cp.async.cg.shared.global [%0], [%1], 16;" :: "r"(dst), "l"(src));
}
__device__ __forceinline__ void cp_commit() {
    asm volatile("cp.async.commit_group;" ::: "memory");
}
template <int N>
__device__ __forceinline__ void cp_wait() {
    asm volatile("cp.async.wait_group %0;" :: "n"(N) : "memory");
}
__device__ __forceinline__ void ldsm_x4(uint32_t* r, uint32_t addr) {
    asm volatile("ldmatrix.sync.aligned.m8n8.x4.shared.b16 {%0,%1,%2,%3}, [%4];"
                 : "=r"(r[0]), "=r"(r[1]), "=r"(r[2]), "=r"(r[3]) : "r"(addr));
}
__device__ __forceinline__ void ldsm_x4_t(uint32_t* r, uint32_t addr) {
    asm volatile("ldmatrix.sync.aligned.m8n8.x4.trans.shared.b16 {%0,%1,%2,%3}, [%4];"
                 : "=r"(r[0]), "=r"(r[1]), "=r"(r[2]), "=r"(r[3]) : "r"(addr));
}
__device__ __forceinline__ void mma_f16(float* c, const uint32_t* a, const uint32_t* b) {
    asm volatile(
        "mma.sync.aligned.m16n8k16.row.col.f32.f16.f16.f32 "
        "{%0,%1,%2,%3},{%4,%5,%6,%7},{%8,%9},{%0,%1,%2,%3};"
        : "+f"(c[0]), "+f"(c[1]), "+f"(c[2]), "+f"(c[3])
        : "r"(a[0]), "r"(a[1]), "r"(a[2]), "r"(a[3]), "r"(b[0]), "r"(b[1]));
}

// ============================ fp16 HMMA GEMM =================================
// Same pipeline as R8 (128x128 block, 2x4 warps of 64x32, TKH=32, 6 stages,
// 2 k-tiles per barrier, race-free re-indexed prefetch), with the pair loop
// unrolled 3x so all buffer indices are compile-time constants.
#define TM 128
#define TN 128
#define TKH 32
#define NSTAGE 6
#define A_STG 8192
#define B_STG 8192
#define STG (A_STG + B_STG)
#define SMEM_DYN (NSTAGE * STG)

__device__ __forceinline__ uint32_t a_off(int row, int c16) {
    const int sr = row >> 1;
    const int ch = (row & 1) * 4 + c16;
    return (uint32_t)(sr * 128 + ((ch ^ (sr & 7)) << 4));
}
__device__ __forceinline__ uint32_t b_off(int k, int c16) {
    return (uint32_t)(A_STG + k * 256 + (((c16 & 8) | ((c16 ^ k) & 7)) << 4));
}

template <int OUT_HALF, int RELU>
__global__ __launch_bounds__(256, 2) void hgemm(
    const __half* __restrict__ A, const __half* __restrict__ B,
    const float* __restrict__ bias, void* __restrict__ Cout,
    int M, int N, int K) {

    extern __shared__ char sm[];
    const uint32_t base = smem_u32(sm);
    const int tid  = threadIdx.x;
    const int lane = tid & 31;
    const int warp = tid >> 5;
    const int wm = warp >> 2, wn = warp & 3;
    const int bm0 = blockIdx.y * TM;
    const int bn0 = blockIdx.x * TN;

    uint32_t a_rel[2]; const __half* a_src[2];
    #pragma unroll
    for (int i = 0; i < 2; i++) {
        const int id = tid * 2 + i;
        const int r = id >> 2, c = id & 3;
        a_rel[i] = a_off(r, c);
        a_src[i] = A + (size_t)(bm0 + r) * K + c * 8;
    }
    uint32_t b_rel[2]; const __half* b_src[2];
    #pragma unroll
    for (int i = 0; i < 2; i++) {
        const int id = tid * 2 + i;
        const int k = id >> 4, c = id & 15;
        b_rel[i] = b_off(k, c);
        b_src[i] = B + (size_t)k * N + bn0 + c * 8;
    }

    float acc[4][4][4];
    #pragma unroll
    for (int mi = 0; mi < 4; mi++)
        #pragma unroll
        for (int ni = 0; ni < 4; ni++)
            #pragma unroll
            for (int j = 0; j < 4; j++) acc[mi][ni][j] = 0.f;

    const int T = K / TKH;

    auto stage = [&](int s, int kt) {
        const int k0 = kt * TKH;
        const uint32_t sb = base + s * STG;
        #pragma unroll
        for (int i = 0; i < 2; i++) cp16(sb + a_rel[i], a_src[i] + k0);
        #pragma unroll
        for (int i = 0; i < 2; i++) cp16(sb + b_rel[i], b_src[i] + (size_t)k0 * N);
        cp_commit();
    };

    const int l_lo = lane & 15;
    const int l_hi = lane >> 4;

    auto compute = [&](int bufi) {
        const uint32_t buf = base + bufi * STG;
        #pragma unroll
        for (int ks = 0; ks < 2; ks++) {
            uint32_t af[4][4];
            #pragma unroll
            for (int mi = 0; mi < 4; mi++) {
                const int row = wm * 64 + mi * 16 + l_lo;
                ldsm_x4(af[mi], buf + a_off(row, ks * 2 + l_hi));
            }
            uint32_t bf[4][2];
            #pragma unroll
            for (int p = 0; p < 2; p++) {
                const int kl = ks * 16 + l_lo;
                const int nc = wn * 4 + p * 2 + l_hi;
                uint32_t r[4];
                ldsm_x4_t(r, buf + b_off(kl, nc));
                bf[p * 2][0]     = r[0]; bf[p * 2][1]     = r[1];
                bf[p * 2 + 1][0] = r[2]; bf[p * 2 + 1][1] = r[3];
            }
            #pragma unroll
            for (int mi = 0; mi < 4; mi++)
                #pragma unroll
                for (int ni = 0; ni < 4; ni++)
                    mma_f16(acc[mi][ni], af[mi], bf[ni]);
        }
    };

    // one barrier per 2 k-tiles; prefetch kt+4 -> buf (kt-2)%6, kt+5 -> (kt-1)%6
    auto pair_body = [&](int kt, int c0, int c1, int s0, int s1) {
        cp_wait<2>();
        __syncthreads();
        const int n1 = kt + 4;
        if (n1 < T) stage(s0, n1); else cp_commit();
        compute(c0);
        const int n2 = kt + 5;
        if (n2 < T) stage(s1, n2); else cp_commit();
        compute(c1);
    };

    // prologue: 4 stages in flight
    #pragma unroll
    for (int s = 0; s < 4; s++) stage(s, s);

    int kt = 0;
    for (; kt + 6 <= T; kt += 6) {          // 3 pairs, constant buffer indices
        pair_body(kt,     0, 1, 4, 5);
        pair_body(kt + 2, 2, 3, 0, 1);
        pair_body(kt + 4, 4, 5, 2, 3);
    }
    for (; kt < T; kt += 2)                  // remainder (runs at most twice)
        pair_body(kt, kt % 6, (kt + 1) % 6, (kt + 4) % 6, (kt + 5) % 6);

    // ---- epilogue ----
    #pragma unroll
    for (int mi = 0; mi < 4; mi++) {
        const int r0 = bm0 + wm * 64 + mi * 16 + (lane >> 2);
        #pragma unroll
        for (int ni = 0; ni < 4; ni++) {
            const int cb = bn0 + wn * 32 + ni * 8 + (lane & 3) * 2;
            const float bb0 = bias[cb], bb1 = bias[cb + 1];
            float v0 = acc[mi][ni][0] + bb0;
            float v1 = acc[mi][ni][1] + bb1;
            float v2 = acc[mi][ni][2] + bb0;
            float v3 = acc[mi][ni][3] + bb1;
            if (RELU) {
                v0 = fmaxf(v0, 0.f); v1 = fmaxf(v1, 0.f);
                v2 = fmaxf(v2, 0.f); v3 = fmaxf(v3, 0.f);
            }
            if (OUT_HALF) {
                __half* Ch = (__half*)Cout;
                *(__half2*)&Ch[(size_t)r0 * N + cb]       = __floats2half2_rn(v0, v1);
                *(__half2*)&Ch[(size_t)(r0 + 8) * N + cb] = __floats2half2_rn(v2, v3);
            } else {
                float* Cf = (float*)Cout;
                *(float2*)&Cf[(size_t)r0 * N + cb]       = make_float2(v0, v1);
                *(float2*)&Cf[(size_t)(r0 + 8) * N + cb] = make_float2(v2, v3);
            }
        }
    }
}

// ---------------- convert both W1 and W2 to half (one launch) ----------------
__global__ void k_tohalf2(const float* __restrict__ W1, const float* __restrict__ W2,
                          __half* __restrict__ W1h, __half* __restrict__ W2h) {
    const int n4 = HD * MD / 4;
    const int i = blockIdx.x * blockDim.x + threadIdx.x;
    const float* in; __half* out; int j;
    if (i < n4)      { in = W1; out = W1h; j = i; }
    else if (i < 2 * n4) { in = W2; out = W2h; j = i - n4; }
    else return;
    float4 f = ((const float4*)in)[j];
    ((__half2*)out)[j * 2]     = __floats2half2_rn(f.x, f.y);
    ((__half2*)out)[j * 2 + 1] = __floats2half2_rn(f.z, f.w);
}

// ---------------- K: sum(ru) ---------------------------------------------------
__global__ void k_ru_sum(const float* __restrict__ ru) {
    __shared__ float sh[256];
    float s = 0.f;
    for (int i = threadIdx.x; i < NTOK; i += 256) s += ru[i];
    sh[threadIdx.x] = s;
    __syncthreads();
    for (int o = 128; o > 0; o >>= 1) {
        if (threadIdx.x < o) sh[threadIdx.x] += sh[threadIdx.x + o];
        __syncthreads();
    }
    if (threadIdx.x == 0) g_ru_sum = sh[0];
}

// ------- K: fused gate + mmh = half(w * LN(v+q)), ru_out -----------------------
__global__ void k_ln1g(const float* __restrict__ v, const float* __restrict__ q,
                       const float* __restrict__ g1, const float* __restrict__ b1,
                       const float* __restrict__ att, const float* __restrict__ ru,
                       __half* __restrict__ mmh, float* __restrict__ ru_out) {
    const int t = blockIdx.x;
    const int b = t / SRCN;
    const int s = t - b * SRCN;

    __shared__ float rg_s[SRCN], rn_s[SRCN];
    __shared__ float wv_sh;

    if (threadIdx.x < SRCN) {
        const int j = threadIdx.x;
        const float* arow = att + ((size_t)b * SRCN + j) * SRCN;
        float rg = 0.f;
        #pragma unroll
        for (int k = 0; k < SRCN; k++) rg += arow[k];
        const float base = ru[b * SRCN + j] * GAMMA_F + rg;
        rg_s[j] = rg;
        rn_s[j] = (g_ru_sum == 0.0f) ? base : base / (1.0f + GAMMA_F);
    }
    __syncthreads();
    if (threadIdx.x == 0) {
        float S = 0.f, T = 0.f;
        #pragma unroll
        for (int j = 0; j < SRCN; j++) {
            const float sa = sqrtf(rn_s[j]);
            S += sa;
            T += rn_s[j] * sa;
        }
        const float rn = rn_s[s], rg = rg_s[s];
        const float rm = (rn * S - T > 0.0f) ? 1.0f : 0.0f;
        ru_out[t] = ALPHA_F * rn * rm + INV_ALPHA_F * rn * (1.0f - rm);
        wv_sh     = ALPHA_F * rg * rm + INV_ALPHA_F * rg * (1.0f - rm);
    }

    const int c0 = threadIdx.x * 4;
    const float4 va = *(const float4*)&v[(size_t)t * HD + c0];
    const float4 qa = *(const float4*)&q[(size_t)t * HD + c0];
    float x[4] = {va.x + qa.x, va.y + qa.y, va.z + qa.z, va.w + qa.w};
    float sm1 = x[0] + x[1] + x[2] + x[3];
    float sm2 = x[0]*x[0] + x[1]*x[1] + x[2]*x[2] + x[3]*x[3];

    __shared__ float sh1[8], sh2[8];
    const int lane = threadIdx.x & 31, wid = threadIdx.x >> 5;
    #pragma unroll
    for (int o = 16; o > 0; o >>= 1) {
        sm1 += __shfl_xor_sync(0xffffffffu, sm1, o);
        sm2 += __shfl_xor_sync(0xffffffffu, sm2, o);
    }
    if (lane == 0) { sh1[wid] = sm1; sh2[wid] = sm2; }
    __syncthreads();
    if (threadIdx.x == 0) {
        float a = 0.f, c = 0.f;
        #pragma unroll
        for (int i = 0; i < 8; i++) { a += sh1[i]; c += sh2[i]; }
        sh1[0] = a; sh2[0] = c;
    }
    __syncthreads();
    sm1 = sh1[0]; sm2 = sh2[0];
    const float mu   = sm1 * (1.0f / HD);
    const float var  = sm2 * (1.0f / HD) - mu * mu;
    const float rstd = rsqrtf(var + 1e-6f);
    const float ww   = wv_sh;

    const float4 ga = *(const float4*)&g1[c0];
    const float4 ba = *(const float4*)&b1[c0];
    float y0 = ww * (ga.x * (x[0] - mu) * rstd + ba.x);
    float y1 = ww * (ga.y * (x[1] - mu) * rstd + ba.y);
    float y2 = ww * (ga.z * (x[2] - mu) * rstd + ba.z);
    float y3 = ww * (ga.w * (x[3] - mu) * rstd + ba.w);
    __half2 p0 = __floats2half2_rn(y0, y1);
    __half2 p1 = __floats2half2_rn(y2, y3);
    uint2 packed;
    packed.x = *reinterpret_cast<uint32_t*>(&p0);
    packed.y = *reinterpret_cast<uint32_t*>(&p1);
    *reinterpret_cast<uint2*>(&mmh[(size_t)t * HD + c0]) = packed;
}

// ---------------- K: out = LN(mmh + fc) ----------------------------------------
__global__ void k_ln2(const __half* __restrict__ mmh, const float* __restrict__ fc,
                      const float* __restrict__ g2, const float* __restrict__ b2,
                      float* __restrict__ out) {
    const int t = blockIdx.x;
    const int c0 = threadIdx.x * 4;

    const uint2 hm = *(const uint2*)&mmh[(size_t)t * HD + c0];
    __half2 m0 = *reinterpret_cast<const __half2*>(&hm.x);
    __half2 m1 = *reinterpret_cast<const __half2*>(&hm.y);
    const float2 f0 = __half22float2(m0);
    const float2 f1 = __half22float2(m1);
    const float4 fv = *(const float4*)&fc[(size_t)t * HD + c0];

    float x[4] = {f0.x + fv.x, f0.y + fv.y, f1.x + fv.z, f1.y + fv.w};
    float s  = x[0] + x[1] + x[2] + x[3];
    float s2 = x[0]*x[0] + x[1]*x[1] + x[2]*x[2] + x[3]*x[3];

    __shared__ float sh1[8], sh2[8];
    const int lane = threadIdx.x & 31, wid = threadIdx.x >> 5;
    #pragma unroll
    for (int o = 16; o > 0; o >>= 1) {
        s  += __shfl_xor_sync(0xffffffffu, s,  o);
        s2 += __shfl_xor_sync(0xffffffffu, s2, o);
    }
    if (lane == 0) { sh1[wid] = s; sh2[wid] = s2; }
    __syncthreads();
    if (threadIdx.x == 0) {
        float a = 0.f, b = 0.f;
        #pragma unroll
        for (int i = 0; i < 8; i++) { a += sh1[i]; b += sh2[i]; }
        sh1[0] = a; sh2[0] = b;
    }
    __syncthreads();
    s = sh1[0]; s2 = sh2[0];
    const float mu   = s * (1.0f / HD);
    const float var  = s2 * (1.0f / HD) - mu * mu;
    const float rstd = rsqrtf(var + 1e-6f);

    const float4 ga = *(const float4*)&g2[c0];
    const float4 ba = *(const float4*)&b2[c0];
    float4 o4;
    o4.x = ga.x * (x[0] - mu) * rstd + ba.x;
    o4.y = ga.y * (x[1] - mu) * rstd + ba.y;
    o4.z = ga.z * (x[2] - mu) * rstd + ba.z;
    o4.w = ga.w * (x[3] - mu) * rstd + ba.w;
    *(float4*)&out[(size_t)t * HD + c0] = o4;
}

// ---------------- launch --------------------------------------------------------
extern "C" void kernel_launch(void* const* d_in, const int* in_sizes, int n_in,
                              void* d_out, int out_size) {
    const float* v   = (const float*)d_in[0];
    const float* q   = (const float*)d_in[1];
    const float* att = (const float*)d_in[2];
    const float* ru  = (const float*)d_in[3];
    const float* g1  = (const float*)d_in[4];
    const float* b1  = (const float*)d_in[5];
    const float* g2  = (const float*)d_in[6];
    const float* b2  = (const float*)d_in[7];
    const float* W1  = (const float*)d_in[8];
    const float* c1  = (const float*)d_in[9];
    const float* W2  = (const float*)d_in[10];
    const float* c2  = (const float*)d_in[11];

    float* out    = (float*)d_out;
    float* ru_out = out + (size_t)NTOK * HD;

    void *pmmh, *ph, *pfc, *pw1h, *pw2h;
    cudaGetSymbolAddress(&pmmh, g_mmh);
    cudaGetSymbolAddress(&ph,   g_h);
    cudaGetSymbolAddress(&pfc,  g_fc);
    cudaGetSymbolAddress(&pw1h, g_W1h);
    cudaGetSymbolAddress(&pw2h, g_W2h);

    cudaFuncSetAttribute(hgemm<1, 1>, cudaFuncAttributeMaxDynamicSharedMemorySize, SMEM_DYN);
    cudaFuncSetAttribute(hgemm<0, 0>, cudaFuncAttributeMaxDynamicSharedMemorySize, SMEM_DYN);

    // launch #1: weight converts (both)
    const int nconv = 2 * (HD * MD / 4);
    k_tohalf2<<<(nconv + 255) / 256, 256>>>(W1, W2, (__half*)pw1h, (__half*)pw2h);
    // launch #2: ru sum
    k_ru_sum<<<1, 256>>>(ru);
    // launch #3: fused gate + LN1 (half residual stream)
    k_ln1g<<<NTOK, 256>>>(v, q, g1, b1, att, ru, (__half*)pmmh, ru_out);
    // launch #4: GEMM1 (profiled)
    hgemm<1, 1><<<dim3(MD / TN, NTOK / TM), 256, SMEM_DYN>>>(
        (const __half*)pmmh, (const __half*)pw1h, c1, ph, NTOK, MD, HD);
    // launch #5: GEMM2
    hgemm<0, 0><<<dim3(HD / TN, NTOK / TM), 256, SMEM_DYN>>>(
        (const __half*)ph, (const __half*)pw2h, c2, pfc, NTOK, HD, MD);
    // launch #6: LN2
    k_ln2<<<NTOK, 256>>>((const __half*)pmmh, (const float*)pfc, g2, b2, out);
}

// round 11
// speedup vs baseline: 1.0762x; 1.0031x over previous
#include <cuda_runtime.h>
#include <cuda_fp16.h>
#include <cstdint>

#define BSZ  512
#define SRCN 36
#define HD   1024
#define MD   4096
#define NTOK (BSZ*SRCN)       // 18432
#define ALPHA_F 8.0f
#define INV_ALPHA_F 0.125f
#define GAMMA_F 0.98f

// ---------------- scratch (device globals: allocation-guard safe) ----------
__device__ float g_ru_sum;
__device__ __align__(16) __half g_mmh[(size_t)NTOK * HD];
__device__ __align__(16) __half g_h  [(size_t)NTOK * MD];
__device__ __align__(16) __half g_fch[(size_t)NTOK * HD];
__device__ __align__(16) __half g_W1h[(size_t)HD * MD];
__device__ __align__(16) __half g_W2h[(size_t)MD * HD];

// ---------------- PTX helpers ------------------------------------------------
__device__ __forceinline__ uint32_t smem_u32(const void* p) {
    uint32_t a;
    asm("{ .reg .u64 t; cvta.to.shared.u64 t, %1; cvt.u32.u64 %0, t; }" : "=r"(a) : "l"(p));
    return a;
}
__device__ __forceinline__ void cp16(uint32_t dst, const void* src) {
    asm volatile("cp.async.cg.shared.global [%0], [%1], 16;" :: "r"(dst), "l"(src));
}
__device__ __forceinline__ void cp_commit() {
    asm volatile("cp.async.commit_group;" ::: "memory");
}
template <int N>
__device__ __forceinline__ void cp_wait() {
    asm volatile("cp.async.wait_group %0;" :: "n"(N) : "memory");
}
__device__ __forceinline__ void ldsm_x4(uint32_t* r, uint32_t addr) {
    asm volatile("ldmatrix.sync.aligned.m8n8.x4.shared.b16 {%0,%1,%2,%3}, [%4];"
                 : "=r"(r[0]), "=r"(r[1]), "=r"(r[2]), "=r"(r[3]) : "r"(addr));
}
__device__ __forceinline__ void ldsm_x4_t(uint32_t* r, uint32_t addr) {
    asm volatile("ldmatrix.sync.aligned.m8n8.x4.trans.shared.b16 {%0,%1,%2,%3}, [%4];"
                 : "=r"(r[0]), "=r"(r[1]), "=r"(r[2]), "=r"(r[3]) : "r"(addr));
}
__device__ __forceinline__ void mma_f16(float* c, const uint32_t* a, const uint32_t* b) {
    asm volatile(
        "mma.sync.aligned.m16n8k16.row.col.f32.f16.f16.f32 "
        "{%0,%1,%2,%3},{%4,%5,%6,%7},{%8,%9},{%0,%1,%2,%3};"
        : "+f"(c[0]), "+f"(c[1]), "+f"(c[2]), "+f"(c[3])
        : "r"(a[0]), "r"(a[1]), "r"(a[2]), "r"(a[3]), "r"(b[0]), "r"(b[1]));
}

// ============================ fp16 HMMA GEMM =================================
// R10 champion pipeline: 128x128 block, 2x4 warps of 64x32, TKH=32, 6 stages,
// 2 k-tiles per barrier, race-free re-indexed prefetch, pair loop unrolled 3x.
#define TM 128
#define TN 128
#define TKH 32
#define NSTAGE 6
#define A_STG 8192
#define B_STG 8192
#define STG (A_STG + B_STG)
#define SMEM_DYN (NSTAGE * STG)

__device__ __forceinline__ uint32_t a_off(int row, int c16) {
    const int sr = row >> 1;
    const int ch = (row & 1) * 4 + c16;
    return (uint32_t)(sr * 128 + ((ch ^ (sr & 7)) << 4));
}
__device__ __forceinline__ uint32_t b_off(int k, int c16) {
    return (uint32_t)(A_STG + k * 256 + (((c16 & 8) | ((c16 ^ k) & 7)) << 4));
}

template <int OUT_HALF, int RELU>
__global__ __launch_bounds__(256, 2) void hgemm(
    const __half* __restrict__ A, const __half* __restrict__ B,
    const float* __restrict__ bias, void* __restrict__ Cout,
    int M, int N, int K) {

    extern __shared__ char sm[];
    const uint32_t base = smem_u32(sm);
    const int tid  = threadIdx.x;
    const int lane = tid & 31;
    const int warp = tid >> 5;
    const int wm = warp >> 2, wn = warp & 3;
    const int bm0 = blockIdx.y * TM;
    const int bn0 = blockIdx.x * TN;

    uint32_t a_rel[2]; const __half* a_src[2];
    #pragma unroll
    for (int i = 0; i < 2; i++) {
        const int id = tid * 2 + i;
        const int r = id >> 2, c = id & 3;
        a_rel[i] = a_off(r, c);
        a_src[i] = A + (size_t)(bm0 + r) * K + c * 8;
    }
    uint32_t b_rel[2]; const __half* b_src[2];
    #pragma unroll
    for (int i = 0; i < 2; i++) {
        const int id = tid * 2 + i;
        const int k = id >> 4, c = id & 15;
        b_rel[i] = b_off(k, c);
        b_src[i] = B + (size_t)k * N + bn0 + c * 8;
    }

    float acc[4][4][4];
    #pragma unroll
    for (int mi = 0; mi < 4; mi++)
        #pragma unroll
        for (int ni = 0; ni < 4; ni++)
            #pragma unroll
            for (int j = 0; j < 4; j++) acc[mi][ni][j] = 0.f;

    const int T = K / TKH;

    auto stage = [&](int s, int kt) {
        const int k0 = kt * TKH;
        const uint32_t sb = base + s * STG;
        #pragma unroll
        for (int i = 0; i < 2; i++) cp16(sb + a_rel[i], a_src[i] + k0);
        #pragma unroll
        for (int i = 0; i < 2; i++) cp16(sb + b_rel[i], b_src[i] + (size_t)k0 * N);
        cp_commit();
    };

    const int l_lo = lane & 15;
    const int l_hi = lane >> 4;

    auto compute = [&](int bufi) {
        const uint32_t buf = base + bufi * STG;
        #pragma unroll
        for (int ks = 0; ks < 2; ks++) {
            uint32_t af[4][4];
            #pragma unroll
            for (int mi = 0; mi < 4; mi++) {
                const int row = wm * 64 + mi * 16 + l_lo;
                ldsm_x4(af[mi], buf + a_off(row, ks * 2 + l_hi));
            }
            uint32_t bf[4][2];
            #pragma unroll
            for (int p = 0; p < 2; p++) {
                const int kl = ks * 16 + l_lo;
                const int nc = wn * 4 + p * 2 + l_hi;
                uint32_t r[4];
                ldsm_x4_t(r, buf + b_off(kl, nc));
                bf[p * 2][0]     = r[0]; bf[p * 2][1]     = r[1];
                bf[p * 2 + 1][0] = r[2]; bf[p * 2 + 1][1] = r[3];
            }
            #pragma unroll
            for (int mi = 0; mi < 4; mi++)
                #pragma unroll
                for (int ni = 0; ni < 4; ni++)
                    mma_f16(acc[mi][ni], af[mi], bf[ni]);
        }
    };

    auto pair_body = [&](int kt, int c0, int c1, int s0, int s1) {
        cp_wait<2>();
        __syncthreads();
        const int n1 = kt + 4;
        if (n1 < T) stage(s0, n1); else cp_commit();
        compute(c0);
        const int n2 = kt + 5;
        if (n2 < T) stage(s1, n2); else cp_commit();
        compute(c1);
    };

    #pragma unroll
    for (int s = 0; s < 4; s++) stage(s, s);

    int kt = 0;
    for (; kt + 6 <= T; kt += 6) {
        pair_body(kt,     0, 1, 4, 5);
        pair_body(kt + 2, 2, 3, 0, 1);
        pair_body(kt + 4, 4, 5, 2, 3);
    }
    for (; kt < T; kt += 2)
        pair_body(kt, kt % 6, (kt + 1) % 6, (kt + 4) % 6, (kt + 5) % 6);

    // ---- epilogue ----
    #pragma unroll
    for (int mi = 0; mi < 4; mi++) {
        const int r0 = bm0 + wm * 64 + mi * 16 + (lane >> 2);
        #pragma unroll
        for (int ni = 0; ni < 4; ni++) {
            const int cb = bn0 + wn * 32 + ni * 8 + (lane & 3) * 2;
            const float bb0 = bias[cb], bb1 = bias[cb + 1];
            float v0 = acc[mi][ni][0] + bb0;
            float v1 = acc[mi][ni][1] + bb1;
            float v2 = acc[mi][ni][2] + bb0;
            float v3 = acc[mi][ni][3] + bb1;
            if (RELU) {
                v0 = fmaxf(v0, 0.f); v1 = fmaxf(v1, 0.f);
                v2 = fmaxf(v2, 0.f); v3 = fmaxf(v3, 0.f);
            }
            if (OUT_HALF) {
                __half* Ch = (__half*)Cout;
                *(__half2*)&Ch[(size_t)r0 * N + cb]       = __floats2half2_rn(v0, v1);
                *(__half2*)&Ch[(size_t)(r0 + 8) * N + cb] = __floats2half2_rn(v2, v3);
            } else {
                float* Cf = (float*)Cout;
                *(float2*)&Cf[(size_t)r0 * N + cb]       = make_float2(v0, v1);
                *(float2*)&Cf[(size_t)(r0 + 8) * N + cb] = make_float2(v2, v3);
            }
        }
    }
}

// -------- prep: convert W1+W2 to half, AND compute sum(ru) (last block) -------
#define NCONV (HD * MD / 4)        // float4 quads per weight matrix
#define NCONV_BLKS ((2 * NCONV) / 256)

__global__ void k_prep(const float* __restrict__ W1, const float* __restrict__ W2,
                       __half* __restrict__ W1h, __half* __restrict__ W2h,
                       const float* __restrict__ ru) {
    if (blockIdx.x < NCONV_BLKS) {
        const int i = blockIdx.x * 256 + threadIdx.x;
        const float* in; __half* out; int j;
        if (i < NCONV) { in = W1; out = W1h; j = i; }
        else           { in = W2; out = W2h; j = i - NCONV; }
        float4 f = ((const float4*)in)[j];
        ((__half2*)out)[j * 2]     = __floats2half2_rn(f.x, f.y);
        ((__half2*)out)[j * 2 + 1] = __floats2half2_rn(f.z, f.w);
        return;
    }
    // last block: sum(ru)
    __shared__ float sh[256];
    float s = 0.f;
    for (int i = threadIdx.x; i < NTOK; i += 256) s += ru[i];
    sh[threadIdx.x] = s;
    __syncthreads();
    for (int o = 128; o > 0; o >>= 1) {
        if (threadIdx.x < o) sh[threadIdx.x] += sh[threadIdx.x + o];
        __syncthreads();
    }
    if (threadIdx.x == 0) g_ru_sum = sh[0];
}

// ------- K: fused gate + mmh = half(w * LN(v+q)), ru_out -----------------------
__global__ void k_ln1g(const float* __restrict__ v, const float* __restrict__ q,
                       const float* __restrict__ g1, const float* __restrict__ b1,
                       const float* __restrict__ att, const float* __restrict__ ru,
                       __half* __restrict__ mmh, float* __restrict__ ru_out) {
    const int t = blockIdx.x;
    const int b = t / SRCN;
    const int s = t - b * SRCN;

    __shared__ float rg_s[SRCN], rn_s[SRCN];
    __shared__ float wv_sh;

    if (threadIdx.x < SRCN) {
        const int j = threadIdx.x;
        const float* arow = att + ((size_t)b * SRCN + j) * SRCN;
        float rg = 0.f;
        #pragma unroll
        for (int k = 0; k < SRCN; k++) rg += arow[k];
        const float base = ru[b * SRCN + j] * GAMMA_F + rg;
        rg_s[j] = rg;
        rn_s[j] = (g_ru_sum == 0.0f) ? base : base / (1.0f + GAMMA_F);
    }
    __syncthreads();
    if (threadIdx.x == 0) {
        float S = 0.f, T = 0.f;
        #pragma unroll
        for (int j = 0; j < SRCN; j++) {
            const float sa = sqrtf(rn_s[j]);
            S += sa;
            T += rn_s[j] * sa;
        }
        const float rn = rn_s[s], rg = rg_s[s];
        const float rm = (rn * S - T > 0.0f) ? 1.0f : 0.0f;
        ru_out[t] = ALPHA_F * rn * rm + INV_ALPHA_F * rn * (1.0f - rm);
        wv_sh     = ALPHA_F * rg * rm + INV_ALPHA_F * rg * (1.0f - rm);
    }

    const int c0 = threadIdx.x * 4;
    const float4 va = *(const float4*)&v[(size_t)t * HD + c0];
    const float4 qa = *(const float4*)&q[(size_t)t * HD + c0];
    float x[4] = {va.x + qa.x, va.y + qa.y, va.z + qa.z, va.w + qa.w};
    float sm1 = x[0] + x[1] + x[2] + x[3];
    float sm2 = x[0]*x[0] + x[1]*x[1] + x[2]*x[2] + x[3]*x[3];

    __shared__ float sh1[8], sh2[8];
    const int lane = threadIdx.x & 31, wid = threadIdx.x >> 5;
    #pragma unroll
    for (int o = 16; o > 0; o >>= 1) {
        sm1 += __shfl_xor_sync(0xffffffffu, sm1, o);
        sm2 += __shfl_xor_sync(0xffffffffu, sm2, o);
    }
    if (lane == 0) { sh1[wid] = sm1; sh2[wid] = sm2; }
    __syncthreads();
    if (threadIdx.x == 0) {
        float a = 0.f, c = 0.f;
        #pragma unroll
        for (int i = 0; i < 8; i++) { a += sh1[i]; c += sh2[i]; }
        sh1[0] = a; sh2[0] = c;
    }
    __syncthreads();
    sm1 = sh1[0]; sm2 = sh2[0];
    const float mu   = sm1 * (1.0f / HD);
    const float var  = sm2 * (1.0f / HD) - mu * mu;
    const float rstd = rsqrtf(var + 1e-6f);
    const float ww   = wv_sh;

    const float4 ga = *(const float4*)&g1[c0];
    const float4 ba = *(const float4*)&b1[c0];
    float y0 = ww * (ga.x * (x[0] - mu) * rstd + ba.x);
    float y1 = ww * (ga.y * (x[1] - mu) * rstd + ba.y);
    float y2 = ww * (ga.z * (x[2] - mu) * rstd + ba.z);
    float y3 = ww * (ga.w * (x[3] - mu) * rstd + ba.w);
    __half2 p0 = __floats2half2_rn(y0, y1);
    __half2 p1 = __floats2half2_rn(y2, y3);
    uint2 packed;
    packed.x = *reinterpret_cast<uint32_t*>(&p0);
    packed.y = *reinterpret_cast<uint32_t*>(&p1);
    *reinterpret_cast<uint2*>(&mmh[(size_t)t * HD + c0]) = packed;
}

// ---------------- K: out = LN(mmh + fch) ---------------------------------------
__global__ void k_ln2(const __half* __restrict__ mmh, const __half* __restrict__ fch,
                      const float* __restrict__ g2, const float* __restrict__ b2,
                      float* __restrict__ out) {
    const int t = blockIdx.x;
    const int c0 = threadIdx.x * 4;

    const uint2 hm = *(const uint2*)&mmh[(size_t)t * HD + c0];
    const uint2 hf = *(const uint2*)&fch[(size_t)t * HD + c0];
    const float2 m0 = __half22float2(*reinterpret_cast<const __half2*>(&hm.x));
    const float2 m1 = __half22float2(*reinterpret_cast<const __half2*>(&hm.y));
    const float2 f0 = __half22float2(*reinterpret_cast<const __half2*>(&hf.x));
    const float2 f1 = __half22float2(*reinterpret_cast<const __half2*>(&hf.y));

    float x[4] = {m0.x + f0.x, m0.y + f0.y, m1.x + f1.x, m1.y + f1.y};
    float s  = x[0] + x[1] + x[2] + x[3];
    float s2 = x[0]*x[0] + x[1]*x[1] + x[2]*x[2] + x[3]*x[3];

    __shared__ float sh1[8], sh2[8];
    const int lane = threadIdx.x & 31, wid = threadIdx.x >> 5;
    #pragma unroll
    for (int o = 16; o > 0; o >>= 1) {
        s  += __shfl_xor_sync(0xffffffffu, s,  o);
        s2 += __shfl_xor_sync(0xffffffffu, s2, o);
    }
    if (lane == 0) { sh1[wid] = s; sh2[wid] = s2; }
    __syncthreads();
    if (threadIdx.x == 0) {
        float a = 0.f, b = 0.f;
        #pragma unroll
        for (int i = 0; i < 8; i++) { a += sh1[i]; b += sh2[i]; }
        sh1[0] = a; sh2[0] = b;
    }
    __syncthreads();
    s = sh1[0]; s2 = sh2[0];
    const float mu   = s * (1.0f / HD);
    const float var  = s2 * (1.0f / HD) - mu * mu;
    const float rstd = rsqrtf(var + 1e-6f);

    const float4 ga = *(const float4*)&g2[c0];
    const float4 ba = *(const float4*)&b2[c0];
    float4 o4;
    o4.x = ga.x * (x[0] - mu) * rstd + ba.x;
    o4.y = ga.y * (x[1] - mu) * rstd + ba.y;
    o4.z = ga.z * (x[2] - mu) * rstd + ba.z;
    o4.w = ga.w * (x[3] - mu) * rstd + ba.w;
    *(float4*)&out[(size_t)t * HD + c0] = o4;
}

// ---------------- launch --------------------------------------------------------
extern "C" void kernel_launch(void* const* d_in, const int* in_sizes, int n_in,
                              void* d_out, int out_size) {
    const float* v   = (const float*)d_in[0];
    const float* q   = (const float*)d_in[1];
    const float* att = (const float*)d_in[2];
    const float* ru  = (const float*)d_in[3];
    const float* g1  = (const float*)d_in[4];
    const float* b1  = (const float*)d_in[5];
    const float* g2  = (const float*)d_in[6];
    const float* b2  = (const float*)d_in[7];
    const float* W1  = (const float*)d_in[8];
    const float* c1  = (const float*)d_in[9];
    const float* W2  = (const float*)d_in[10];
    const float* c2  = (const float*)d_in[11];

    float* out    = (float*)d_out;
    float* ru_out = out + (size_t)NTOK * HD;

    void *pmmh, *ph, *pfch, *pw1h, *pw2h;
    cudaGetSymbolAddress(&pmmh, g_mmh);
    cudaGetSymbolAddress(&ph,   g_h);
    cudaGetSymbolAddress(&pfch, g_fch);
    cudaGetSymbolAddress(&pw1h, g_W1h);
    cudaGetSymbolAddress(&pw2h, g_W2h);

    cudaFuncSetAttribute(hgemm<1, 1>, cudaFuncAttributeMaxDynamicSharedMemorySize, SMEM_DYN);
    cudaFuncSetAttribute(hgemm<1, 0>, cudaFuncAttributeMaxDynamicSharedMemorySize, SMEM_DYN);

    // launch #1: weight converts + ru sum (fused)
    k_prep<<<NCONV_BLKS + 1, 256>>>(W1, W2, (__half*)pw1h, (__half*)pw2h, ru);
    // launch #2: fused gate + LN1 (half residual stream)
    k_ln1g<<<NTOK, 256>>>(v, q, g1, b1, att, ru, (__half*)pmmh, ru_out);
    // launch #3: GEMM1
    hgemm<1, 1><<<dim3(MD / TN, NTOK / TM), 256, SMEM_DYN>>>(
        (const __half*)pmmh, (const __half*)pw1h, c1, ph, NTOK, MD, HD);
    // launch #4: GEMM2 (profiled this round)
    hgemm<1, 0><<<dim3(HD / TN, NTOK / TM), 256, SMEM_DYN>>>(
        (const __half*)ph, (const __half*)pw2h, c2, pfch, NTOK, HD, MD);
    // launch #5: LN2
    k_ln2<<<NTOK, 256>>>((const __half*)pmmh, (const __half*)pfch, g2, b2, out);
}

// round 12
// speedup vs baseline: 1.1286x; 1.0487x over previous
#include <cuda_runtime.h>
#include <cuda_fp16.h>
#include <cstdint>

#define BSZ  512
#define SRCN 36
#define HD   1024
#define MD   4096
#define NTOK (BSZ*SRCN)       // 18432
#define ALPHA_F 8.0f
#define INV_ALPHA_F 0.125f
#define GAMMA_F 0.98f

// ---------------- scratch (device globals: allocation-guard safe) ----------
__device__ float g_ru_sum;
__device__ float g_w[NTOK];
__device__ __align__(16) __half g_mmh[(size_t)NTOK * HD];
__device__ __align__(16) __half g_h  [(size_t)NTOK * MD];
__device__ __align__(16) __half g_fch[(size_t)NTOK * HD];
__device__ __align__(16) __half g_W1h[(size_t)HD * MD];
__device__ __align__(16) __half g_W2h[(size_t)MD * HD];

// ---------------- PTX helpers ------------------------------------------------
__device__ __forceinline__ uint32_t smem_u32(const void* p) {
    uint32_t a;
    asm("{ .reg .u64 t; cvta.to.shared.u64 t, %1; cvt.u32.u64 %0, t; }" : "=r"(a) : "l"(p));
    return a;
}
__device__ __forceinline__ void cp16(uint32_t dst, const void* src) {
    asm volatile("cp.async.cg.shared.global [%0], [%1], 16;" :: "r"(dst), "l"(src));
}
__device__ __forceinline__ void cp_commit() {
    asm volatile("cp.async.commit_group;" ::: "memory");
}
template <int N>
__device__ __forceinline__ void cp_wait() {
    asm volatile("cp.async.wait_group %0;" :: "n"(N) : "memory");
}
__device__ __forceinline__ void ldsm_x4(uint32_t* r, uint32_t addr) {
    asm volatile("ldmatrix.sync.aligned.m8n8.x4.shared.b16 {%0,%1,%2,%3}, [%4];"
                 : "=r"(r[0]), "=r"(r[1]), "=r"(r[2]), "=r"(r[3]) : "r"(addr));
}
__device__ __forceinline__ void ldsm_x4_t(uint32_t* r, uint32_t addr) {
    asm volatile("ldmatrix.sync.aligned.m8n8.x4.trans.shared.b16 {%0,%1,%2,%3}, [%4];"
                 : "=r"(r[0]), "=r"(r[1]), "=r"(r[2]), "=r"(r[3]) : "r"(addr));
}
__device__ __forceinline__ void mma_f16(float* c, const uint32_t* a, const uint32_t* b) {
    asm volatile(
        "mma.sync.aligned.m16n8k16.row.col.f32.f16.f16.f32 "
        "{%0,%1,%2,%3},{%4,%5,%6,%7},{%8,%9},{%0,%1,%2,%3};"
        : "+f"(c[0]), "+f"(c[1]), "+f"(c[2]), "+f"(c[3])
        : "r"(a[0]), "r"(a[1]), "r"(a[2]), "r"(a[3]), "r"(b[0]), "r"(b[1]));
}

// ============================ fp16 HMMA GEMM =================================
// R10 champion pipeline: 128x128 block, 2x4 warps of 64x32, TKH=32, 6 stages,
// 2 k-tiles per barrier, race-free re-indexed prefetch, pair loop unrolled 3x.
#define TM 128
#define TN 128
#define TKH 32
#define NSTAGE 6
#define A_STG 8192
#define B_STG 8192
#define STG (A_STG + B_STG)
#define SMEM_DYN (NSTAGE * STG)

__device__ __forceinline__ uint32_t a_off(int row, int c16) {
    const int sr = row >> 1;
    const int ch = (row & 1) * 4 + c16;
    return (uint32_t)(sr * 128 + ((ch ^ (sr & 7)) << 4));
}
__device__ __forceinline__ uint32_t b_off(int k, int c16) {
    return (uint32_t)(A_STG + k * 256 + (((c16 & 8) | ((c16 ^ k) & 7)) << 4));
}

template <int OUT_HALF, int RELU>
__global__ __launch_bounds__(256, 2) void hgemm(
    const __half* __restrict__ A, const __half* __restrict__ B,
    const float* __restrict__ bias, void* __restrict__ Cout,
    int M, int N, int K) {

    extern __shared__ char sm[];
    const uint32_t base = smem_u32(sm);
    const int tid  = threadIdx.x;
    const int lane = tid & 31;
    const int warp = tid >> 5;
    const int wm = warp >> 2, wn = warp & 3;
    const int bm0 = blockIdx.y * TM;
    const int bn0 = blockIdx.x * TN;

    uint32_t a_rel[2]; const __half* a_src[2];
    #pragma unroll
    for (int i = 0; i < 2; i++) {
        const int id = tid * 2 + i;
        const int r = id >> 2, c = id & 3;
        a_rel[i] = a_off(r, c);
        a_src[i] = A + (size_t)(bm0 + r) * K + c * 8;
    }
    uint32_t b_rel[2]; const __half* b_src[2];
    #pragma unroll
    for (int i = 0; i < 2; i++) {
        const int id = tid * 2 + i;
        const int k = id >> 4, c = id & 15;
        b_rel[i] = b_off(k, c);
        b_src[i] = B + (size_t)k * N + bn0 + c * 8;
    }

    float acc[4][4][4];
    #pragma unroll
    for (int mi = 0; mi < 4; mi++)
        #pragma unroll
        for (int ni = 0; ni < 4; ni++)
            #pragma unroll
            for (int j = 0; j < 4; j++) acc[mi][ni][j] = 0.f;

    const int T = K / TKH;

    auto stage = [&](int s, int kt) {
        const int k0 = kt * TKH;
        const uint32_t sb = base + s * STG;
        #pragma unroll
        for (int i = 0; i < 2; i++) cp16(sb + a_rel[i], a_src[i] + k0);
        #pragma unroll
        for (int i = 0; i < 2; i++) cp16(sb + b_rel[i], b_src[i] + (size_t)k0 * N);
        cp_commit();
    };

    const int l_lo = lane & 15;
    const int l_hi = lane >> 4;

    auto compute = [&](int bufi) {
        const uint32_t buf = base + bufi * STG;
        #pragma unroll
        for (int ks = 0; ks < 2; ks++) {
            uint32_t af[4][4];
            #pragma unroll
            for (int mi = 0; mi < 4; mi++) {
                const int row = wm * 64 + mi * 16 + l_lo;
                ldsm_x4(af[mi], buf + a_off(row, ks * 2 + l_hi));
            }
            uint32_t bf[4][2];
            #pragma unroll
            for (int p = 0; p < 2; p++) {
                const int kl = ks * 16 + l_lo;
                const int nc = wn * 4 + p * 2 + l_hi;
                uint32_t r[4];
                ldsm_x4_t(r, buf + b_off(kl, nc));
                bf[p * 2][0]     = r[0]; bf[p * 2][1]     = r[1];
                bf[p * 2 + 1][0] = r[2]; bf[p * 2 + 1][1] = r[3];
            }
            #pragma unroll
            for (int mi = 0; mi < 4; mi++)
                #pragma unroll
                for (int ni = 0; ni < 4; ni++)
                    mma_f16(acc[mi][ni], af[mi], bf[ni]);
        }
    };

    auto pair_body = [&](int kt, int c0, int c1, int s0, int s1) {
        cp_wait<2>();
        __syncthreads();
        const int n1 = kt + 4;
        if (n1 < T) stage(s0, n1); else cp_commit();
        compute(c0);
        const int n2 = kt + 5;
        if (n2 < T) stage(s1, n2); else cp_commit();
        compute(c1);
    };

    #pragma unroll
    for (int s = 0; s < 4; s++) stage(s, s);

    int kt = 0;
    for (; kt + 6 <= T; kt += 6) {
        pair_body(kt,     0, 1, 4, 5);
        pair_body(kt + 2, 2, 3, 0, 1);
        pair_body(kt + 4, 4, 5, 2, 3);
    }
    for (; kt < T; kt += 2)
        pair_body(kt, kt % 6, (kt + 1) % 6, (kt + 4) % 6, (kt + 5) % 6);

    // ---- epilogue ----
    #pragma unroll
    for (int mi = 0; mi < 4; mi++) {
        const int r0 = bm0 + wm * 64 + mi * 16 + (lane >> 2);
        #pragma unroll
        for (int ni = 0; ni < 4; ni++) {
            const int cb = bn0 + wn * 32 + ni * 8 + (lane & 3) * 2;
            const float bb0 = bias[cb], bb1 = bias[cb + 1];
            float v0 = acc[mi][ni][0] + bb0;
            float v1 = acc[mi][ni][1] + bb1;
            float v2 = acc[mi][ni][2] + bb0;
            float v3 = acc[mi][ni][3] + bb1;
            if (RELU) {
                v0 = fmaxf(v0, 0.f); v1 = fmaxf(v1, 0.f);
                v2 = fmaxf(v2, 0.f); v3 = fmaxf(v3, 0.f);
            }
            if (OUT_HALF) {
                __half* Ch = (__half*)Cout;
                *(__half2*)&Ch[(size_t)r0 * N + cb]       = __floats2half2_rn(v0, v1);
                *(__half2*)&Ch[(size_t)(r0 + 8) * N + cb] = __floats2half2_rn(v2, v3);
            } else {
                float* Cf = (float*)Cout;
                *(float2*)&Cf[(size_t)r0 * N + cb]       = make_float2(v0, v1);
                *(float2*)&Cf[(size_t)(r0 + 8) * N + cb] = make_float2(v2, v3);
            }
        }
    }
}

// -------- prep: convert W1+W2 to half, AND compute sum(ru) (last block) -------
#define NCONV (HD * MD / 4)
#define NCONV_BLKS ((2 * NCONV) / 256)

__global__ void k_prep(const float* __restrict__ W1, const float* __restrict__ W2,
                       __half* __restrict__ W1h, __half* __restrict__ W2h,
                       const float* __restrict__ ru) {
    if (blockIdx.x < NCONV_BLKS) {
        const int i = blockIdx.x * 256 + threadIdx.x;
        const float* in; __half* out; int j;
        if (i < NCONV) { in = W1; out = W1h; j = i; }
        else           { in = W2; out = W2h; j = i - NCONV; }
        float4 f = ((const float4*)in)[j];
        ((__half2*)out)[j * 2]     = __floats2half2_rn(f.x, f.y);
        ((__half2*)out)[j * 2 + 1] = __floats2half2_rn(f.z, f.w);
        return;
    }
    __shared__ float sh[256];
    float s = 0.f;
    for (int i = threadIdx.x; i < NTOK; i += 256) s += ru[i];
    sh[threadIdx.x] = s;
    __syncthreads();
    for (int o = 128; o > 0; o >>= 1) {
        if (threadIdx.x < o) sh[threadIdx.x] += sh[threadIdx.x + o];
        __syncthreads();
    }
    if (threadIdx.x == 0) g_ru_sum = sh[0];
}

// ---------------- K: per-batch gate (w, ru_out) --------------------------------
__global__ void k_gate(const float* __restrict__ att, const float* __restrict__ ru,
                       float* __restrict__ ru_out, float* __restrict__ w_out) {
    const int b = blockIdx.x;
    __shared__ float rg_s[SRCN], rn_s[SRCN], sa_s[SRCN];
    __shared__ float S_sh, T_sh;

    if (threadIdx.x < SRCN) {
        const int s = threadIdx.x;
        const float* arow = att + ((size_t)b * SRCN + s) * SRCN;
        float rg = 0.f;
        #pragma unroll
        for (int j = 0; j < SRCN; j++) rg += arow[j];
        const float base = ru[b * SRCN + s] * GAMMA_F + rg;
        const float rn = (g_ru_sum == 0.0f) ? base : base / (1.0f + GAMMA_F);
        rg_s[s] = rg;
        rn_s[s] = rn;
        sa_s[s] = sqrtf(rn);
    }
    __syncthreads();
    if (threadIdx.x == 0) {
        float S = 0.f, T = 0.f;
        #pragma unroll
        for (int j = 0; j < SRCN; j++) { S += sa_s[j]; T += rn_s[j] * sa_s[j]; }
        S_sh = S; T_sh = T;
    }
    __syncthreads();
    if (threadIdx.x < SRCN) {
        const int s = threadIdx.x;
        const float rn = rn_s[s], rg = rg_s[s];
        const float rm = (rn * S_sh - T_sh > 0.0f) ? 1.0f : 0.0f;
        ru_out[b * SRCN + s] = ALPHA_F * rn * rm + INV_ALPHA_F * rn * (1.0f - rm);
        w_out [b * SRCN + s] = ALPHA_F * rg * rm + INV_ALPHA_F * rg * (1.0f - rm);
    }
}

// ---------------- K: mmh = half(w * LN(v+q)) — pure streaming -------------------
__global__ void k_ln1(const float* __restrict__ v, const float* __restrict__ q,
                      const float* __restrict__ g1, const float* __restrict__ b1,
                      const float* __restrict__ w, __half* __restrict__ mmh) {
    const int t = blockIdx.x;
    const int c0 = threadIdx.x * 4;
    const float4 va = *(const float4*)&v[(size_t)t * HD + c0];
    const float4 qa = *(const float4*)&q[(size_t)t * HD + c0];
    float x[4] = {va.x + qa.x, va.y + qa.y, va.z + qa.z, va.w + qa.w};
    float sm1 = x[0] + x[1] + x[2] + x[3];
    float sm2 = x[0]*x[0] + x[1]*x[1] + x[2]*x[2] + x[3]*x[3];

    __shared__ float sh1[8], sh2[8];
    const int lane = threadIdx.x & 31, wid = threadIdx.x >> 5;
    #pragma unroll
    for (int o = 16; o > 0; o >>= 1) {
        sm1 += __shfl_xor_sync(0xffffffffu, sm1, o);
        sm2 += __shfl_xor_sync(0xffffffffu, sm2, o);
    }
    if (lane == 0) { sh1[wid] = sm1; sh2[wid] = sm2; }
    __syncthreads();
    sm1 = 0.f; sm2 = 0.f;
    #pragma unroll
    for (int i = 0; i < 8; i++) { sm1 += sh1[i]; sm2 += sh2[i]; }

    const float mu   = sm1 * (1.0f / HD);
    const float var  = sm2 * (1.0f / HD) - mu * mu;
    const float rstd = rsqrtf(var + 1e-6f);
    const float ww   = __ldg(&w[t]);

    const float4 ga = *(const float4*)&g1[c0];
    const float4 ba = *(const float4*)&b1[c0];
    float y0 = ww * (ga.x * (x[0] - mu) * rstd + ba.x);
    float y1 = ww * (ga.y * (x[1] - mu) * rstd + ba.y);
    float y2 = ww * (ga.z * (x[2] - mu) * rstd + ba.z);
    float y3 = ww * (ga.w * (x[3] - mu) * rstd + ba.w);
    __half2 p0 = __floats2half2_rn(y0, y1);
    __half2 p1 = __floats2half2_rn(y2, y3);
    uint2 packed;
    packed.x = *reinterpret_cast<uint32_t*>(&p0);
    packed.y = *reinterpret_cast<uint32_t*>(&p1);
    *reinterpret_cast<uint2*>(&mmh[(size_t)t * HD + c0]) = packed;
}

// ---------------- K: out = LN(mmh + fch) ---------------------------------------
__global__ void k_ln2(const __half* __restrict__ mmh, const __half* __restrict__ fch,
                      const float* __restrict__ g2, const float* __restrict__ b2,
                      float* __restrict__ out) {
    const int t = blockIdx.x;
    const int c0 = threadIdx.x * 4;

    const uint2 hm = *(const uint2*)&mmh[(size_t)t * HD + c0];
    const uint2 hf = *(const uint2*)&fch[(size_t)t * HD + c0];
    const float2 m0 = __half22float2(*reinterpret_cast<const __half2*>(&hm.x));
    const float2 m1 = __half22float2(*reinterpret_cast<const __half2*>(&hm.y));
    const float2 f0 = __half22float2(*reinterpret_cast<const __half2*>(&hf.x));
    const float2 f1 = __half22float2(*reinterpret_cast<const __half2*>(&hf.y));

    float x[4] = {m0.x + f0.x, m0.y + f0.y, m1.x + f1.x, m1.y + f1.y};
    float s  = x[0] + x[1] + x[2] + x[3];
    float s2 = x[0]*x[0] + x[1]*x[1] + x[2]*x[2] + x[3]*x[3];

    __shared__ float sh1[8], sh2[8];
    const int lane = threadIdx.x & 31, wid = threadIdx.x >> 5;
    #pragma unroll
    for (int o = 16; o > 0; o >>= 1) {
        s  += __shfl_xor_sync(0xffffffffu, s,  o);
        s2 += __shfl_xor_sync(0xffffffffu, s2, o);
    }
    if (lane == 0) { sh1[wid] = s; sh2[wid] = s2; }
    __syncthreads();
    s = 0.f; s2 = 0.f;
    #pragma unroll
    for (int i = 0; i < 8; i++) { s += sh1[i]; s2 += sh2[i]; }

    const float mu   = s * (1.0f / HD);
    const float var  = s2 * (1.0f / HD) - mu * mu;
    const float rstd = rsqrtf(var + 1e-6f);

    const float4 ga = *(const float4*)&g2[c0];
    const float4 ba = *(const float4*)&b2[c0];
    float4 o4;
    o4.x = ga.x * (x[0] - mu) * rstd + ba.x;
    o4.y = ga.y * (x[1] - mu) * rstd + ba.y;
    o4.z = ga.z * (x[2] - mu) * rstd + ba.z;
    o4.w = ga.w * (x[3] - mu) * rstd + ba.w;
    *(float4*)&out[(size_t)t * HD + c0] = o4;
}

// ---------------- launch --------------------------------------------------------
extern "C" void kernel_launch(void* const* d_in, const int* in_sizes, int n_in,
                              void* d_out, int out_size) {
    const float* v   = (const float*)d_in[0];
    const float* q   = (const float*)d_in[1];
    const float* att = (const float*)d_in[2];
    const float* ru  = (const float*)d_in[3];
    const float* g1  = (const float*)d_in[4];
    const float* b1  = (const float*)d_in[5];
    const float* g2  = (const float*)d_in[6];
    const float* b2  = (const float*)d_in[7];
    const float* W1  = (const float*)d_in[8];
    const float* c1  = (const float*)d_in[9];
    const float* W2  = (const float*)d_in[10];
    const float* c2  = (const float*)d_in[11];

    float* out    = (float*)d_out;
    float* ru_out = out + (size_t)NTOK * HD;

    void *pmmh, *ph, *pfch, *pw1h, *pw2h, *pw;
    cudaGetSymbolAddress(&pmmh, g_mmh);
    cudaGetSymbolAddress(&ph,   g_h);
    cudaGetSymbolAddress(&pfch, g_fch);
    cudaGetSymbolAddress(&pw1h, g_W1h);
    cudaGetSymbolAddress(&pw2h, g_W2h);
    cudaGetSymbolAddress(&pw,   g_w);

    cudaFuncSetAttribute(hgemm<1, 1>, cudaFuncAttributeMaxDynamicSharedMemorySize, SMEM_DYN);
    cudaFuncSetAttribute(hgemm<1, 0>, cudaFuncAttributeMaxDynamicSharedMemorySize, SMEM_DYN);

    // launch #1: weight converts + ru sum (fused)
    k_prep<<<NCONV_BLKS + 1, 256>>>(W1, W2, (__half*)pw1h, (__half*)pw2h, ru);
    // launch #2: per-batch gate
    k_gate<<<BSZ, 64>>>(att, ru, ru_out, (float*)pw);
    // launch #3: pure streaming LN1
    k_ln1<<<NTOK, 256>>>(v, q, g1, b1, (const float*)pw, (__half*)pmmh);
    // launch #4: GEMM1 (profiled)
    hgemm<1, 1><<<dim3(MD / TN, NTOK / TM), 256, SMEM_DYN>>>(
        (const __half*)pmmh, (const __half*)pw1h, c1, ph, NTOK, MD, HD);
    // launch #5: GEMM2
    hgemm<1, 0><<<dim3(HD / TN, NTOK / TM), 256, SMEM_DYN>>>(
        (const __half*)ph, (const __half*)pw2h, c2, pfch, NTOK, HD, MD);
    // launch #6: LN2
    k_ln2<<<NTOK, 256>>>((const __half*)pmmh, (const __half*)pfch, g2, b2, out);
}